// round 2
// baseline (speedup 1.0000x reference)
#include <cuda_runtime.h>

#define BB 64
#define TT 512
#define II 512
#define HH 1024
#define NCTA_DIR 64   // CTAs per direction; 128 total <= 148 SMs -> all co-resident

// ---------------- scratch (device globals; no allocations allowed) ----------
__device__ float g_Xrz[2][TT][BB][2 * HH]; // precomputed x@W_xr|x@W_xz (+bias), combined cols
__device__ float g_Xh [2][TT][BB][HH];     // precomputed x@W_xh (+bias)
__device__ float g_h  [2][BB][HH];         // current hidden state per direction
__device__ float g_RH [2][BB][HH];         // R * h   (phase1 -> phase2)
__device__ float g_Z  [2][BB][HH];         // Z gate  (phase1 -> phase2)
__device__ unsigned g_bar_count[2];
__device__ unsigned g_bar_gen[2];

// ------------- per-direction software grid barrier (generation-based) -------
__device__ __forceinline__ void dir_barrier(int dir) {
    __syncthreads();
    if (threadIdx.x == 0) {
        volatile unsigned* vgen = (volatile unsigned*)&g_bar_gen[dir];
        unsigned my = *vgen;
        __threadfence();
        unsigned a = atomicAdd(&g_bar_count[dir], 1u);
        if (a == NCTA_DIR - 1) {
            g_bar_count[dir] = 0;
            __threadfence();
            atomicAdd(&g_bar_gen[dir], 1u);
        } else {
            while (*vgen == my) { }
            __threadfence();
        }
    }
    __syncthreads();
}

// ---------------- input projection: 6x GEMM (32768x512)@(512x1024)+bias -----
// CTA: 256 threads -> 64x32 tile, 8 outputs/thread (8 rows x 1 col)
__global__ void __launch_bounds__(256) inproj_kernel(
    const float* __restrict__ x,
    const float* __restrict__ Wr_f, const float* __restrict__ br_f,
    const float* __restrict__ Wz_f, const float* __restrict__ bz_f,
    const float* __restrict__ Wh_f, const float* __restrict__ bh_f,
    const float* __restrict__ Wr_b, const float* __restrict__ br_b,
    const float* __restrict__ Wz_b, const float* __restrict__ bz_b,
    const float* __restrict__ Wh_b, const float* __restrict__ bh_b)
{
    const int mat  = blockIdx.z;   // 0..5 : dir*3 + gate
    const int dir  = mat / 3;
    const int gate = mat % 3;      // 0=r, 1=z, 2=h
    const float* W; const float* bias;
    switch (mat) {
        case 0: W = Wr_f; bias = br_f; break;
        case 1: W = Wz_f; bias = bz_f; break;
        case 2: W = Wh_f; bias = bh_f; break;
        case 3: W = Wr_b; bias = br_b; break;
        case 4: W = Wz_b; bias = bz_b; break;
        default: W = Wh_b; bias = bh_b; break;
    }

    const int mTile = blockIdx.x;           // 512 row tiles of 64
    const int cTile = blockIdx.y;           // 32 col tiles of 32
    const int lane  = threadIdx.x & 31;
    const int rg    = (threadIdx.x >> 5) * 8;
    const int j     = cTile * 32 + lane;

    __shared__ float xs[64][64];
    float acc[8] = {0.f,0.f,0.f,0.f,0.f,0.f,0.f,0.f};

    const float* xbase = x + (size_t)(mTile * 64) * II;

    #pragma unroll 1
    for (int kb = 0; kb < II; kb += 64) {
        // stage 64x64 x-tile (coalesced float4)
        #pragma unroll
        for (int u = 0; u < 4; ++u) {
            int e  = threadIdx.x + 256 * u;     // 0..1023
            int r  = e >> 4;
            int c4 = (e & 15) * 4;
            *(float4*)&xs[r][c4] = *(const float4*)(xbase + r * II + kb + c4);
        }
        __syncthreads();
        #pragma unroll
        for (int k4 = 0; k4 < 16; ++k4) {
            const int k = kb + 4 * k4;
            const float w0 = W[(k + 0) * HH + j];
            const float w1 = W[(k + 1) * HH + j];
            const float w2 = W[(k + 2) * HH + j];
            const float w3 = W[(k + 3) * HH + j];
            #pragma unroll
            for (int r = 0; r < 8; ++r) {
                float4 hv = *(const float4*)&xs[rg + r][4 * k4];
                acc[r] = fmaf(hv.x, w0, acc[r]);
                acc[r] = fmaf(hv.y, w1, acc[r]);
                acc[r] = fmaf(hv.z, w2, acc[r]);
                acc[r] = fmaf(hv.w, w3, acc[r]);
            }
        }
        __syncthreads();
    }

    const float bv = bias[j];
    #pragma unroll
    for (int r = 0; r < 8; ++r) {
        int row = mTile * 64 + rg + r;   // row = b*T + t
        int b   = row >> 9;              // /512
        int t   = row & (TT - 1);
        float v = acc[r] + bv;
        if (gate == 0)      g_Xrz[dir][t][b][j]      = v;
        else if (gate == 1) g_Xrz[dir][t][b][HH + j] = v;
        else                g_Xh [dir][t][b][j]      = v;
    }
}

// ---------------- persistent bidirectional GRU recurrence -------------------
// 128 CTAs x 256 threads. dir = bid/64. Per step:
//   phase1: [R|Z] = sigmoid(h @ [W_hr|W_hz] + xrz); RH = R*h   (64x2048, K=1024)
//   barrier(dir)
//   phase2: htil = tanh(RH @ W_hh + xh); h = Z*htil + (1-Z)*h  (64x1024, K=1024)
//   barrier(dir)
__global__ void __launch_bounds__(256) gru_rec_kernel(
    const float* __restrict__ hf0, const float* __restrict__ hb0,
    const float* __restrict__ Whr_f, const float* __restrict__ Whz_f, const float* __restrict__ Whh_f,
    const float* __restrict__ Whr_b, const float* __restrict__ Whz_b, const float* __restrict__ Whh_b,
    float* __restrict__ out)
{
    const int dir = blockIdx.x >> 6;
    const int c   = blockIdx.x & 63;

    const float* __restrict__ Whr = dir ? Whr_b : Whr_f;
    const float* __restrict__ Whz = dir ? Whz_b : Whz_f;
    const float* __restrict__ Whh = dir ? Whh_b : Whh_f;
    const float* __restrict__ h0  = dir ? hb0   : hf0;

    float* __restrict__ hstate = &g_h [dir][0][0];
    float* __restrict__ RH     = &g_RH[dir][0][0];
    float* __restrict__ Zb     = &g_Z [dir][0][0];

    // init hidden state from h_prev (re-done every replay: deterministic)
    {
        int base = c * 1024;   // 65536 elems / 64 CTAs
        #pragma unroll
        for (int u = 0; u < 4; ++u)
            hstate[base + u * 256 + threadIdx.x] = h0[base + u * 256 + threadIdx.x];
    }
    dir_barrier(dir);

    __shared__ float ts[64][64];

    // phase1 geometry: 32 cols/CTA over combined 2048 cols; 8 rows/thread
    const int lane1 = threadIdx.x & 31;
    const int rg1   = (threadIdx.x >> 5) * 8;
    const int jj    = c * 32 + lane1;            // 0..2047 combined [R|Z]
    const float* __restrict__ Wg = (jj < HH) ? Whr : Whz;
    const int jw    = jj & (HH - 1);

    // phase2 geometry: 16 cols/CTA over 1024 cols; 4 rows/thread
    const int lane2 = threadIdx.x & 15;
    const int rg2   = (threadIdx.x >> 4) * 4;
    const int j2    = c * 16 + lane2;

    for (int step = 0; step < TT; ++step) {
        const int t = dir ? (TT - 1 - step) : step;

        // ------------------ phase 1 ------------------
        float acc[8] = {0.f,0.f,0.f,0.f,0.f,0.f,0.f,0.f};
        #pragma unroll 1
        for (int kb = 0; kb < HH; kb += 64) {
            #pragma unroll
            for (int u = 0; u < 4; ++u) {
                int e  = threadIdx.x + 256 * u;
                int r  = e >> 4;
                int c4 = (e & 15) * 4;
                *(float4*)&ts[r][c4] = *(const float4*)&hstate[r * HH + kb + c4];
            }
            __syncthreads();
            #pragma unroll
            for (int k4 = 0; k4 < 16; ++k4) {
                const int k = kb + 4 * k4;
                const float w0 = Wg[(k + 0) * HH + jw];
                const float w1 = Wg[(k + 1) * HH + jw];
                const float w2 = Wg[(k + 2) * HH + jw];
                const float w3 = Wg[(k + 3) * HH + jw];
                #pragma unroll
                for (int r = 0; r < 8; ++r) {
                    float4 hv = *(const float4*)&ts[rg1 + r][4 * k4];
                    acc[r] = fmaf(hv.x, w0, acc[r]);
                    acc[r] = fmaf(hv.y, w1, acc[r]);
                    acc[r] = fmaf(hv.z, w2, acc[r]);
                    acc[r] = fmaf(hv.w, w3, acc[r]);
                }
            }
            __syncthreads();
        }
        {
            const float* __restrict__ xrz = &g_Xrz[dir][t][0][0];
            #pragma unroll
            for (int r = 0; r < 8; ++r) {
                const int b = rg1 + r;
                float pre = acc[r] + xrz[b * (2 * HH) + jj];
                float s   = 1.f / (1.f + __expf(-pre));
                if (jj < HH) RH[b * HH + jw] = s * hstate[b * HH + jw];
                else         Zb[b * HH + jw] = s;
            }
        }
        dir_barrier(dir);

        // ------------------ phase 2 ------------------
        float a2[4] = {0.f,0.f,0.f,0.f};
        #pragma unroll 1
        for (int kb = 0; kb < HH; kb += 64) {
            #pragma unroll
            for (int u = 0; u < 4; ++u) {
                int e  = threadIdx.x + 256 * u;
                int r  = e >> 4;
                int c4 = (e & 15) * 4;
                *(float4*)&ts[r][c4] = *(const float4*)&RH[r * HH + kb + c4];
            }
            __syncthreads();
            #pragma unroll
            for (int k4 = 0; k4 < 16; ++k4) {
                const int k = kb + 4 * k4;
                const float w0 = Whh[(k + 0) * HH + j2];
                const float w1 = Whh[(k + 1) * HH + j2];
                const float w2 = Whh[(k + 2) * HH + j2];
                const float w3 = Whh[(k + 3) * HH + j2];
                #pragma unroll
                for (int r = 0; r < 4; ++r) {
                    float4 hv = *(const float4*)&ts[rg2 + r][4 * k4];
                    a2[r] = fmaf(hv.x, w0, a2[r]);
                    a2[r] = fmaf(hv.y, w1, a2[r]);
                    a2[r] = fmaf(hv.z, w2, a2[r]);
                    a2[r] = fmaf(hv.w, w3, a2[r]);
                }
            }
            __syncthreads();
        }
        {
            const float* __restrict__ xh = &g_Xh[dir][t][0][0];
            #pragma unroll
            for (int r = 0; r < 4; ++r) {
                const int b = rg2 + r;
                float pre  = a2[r] + xh[b * HH + j2];
                float htil = tanhf(pre);
                float z    = Zb[b * HH + j2];
                float hold = hstate[b * HH + j2];
                float hnew = z * htil + (1.f - z) * hold;
                hstate[b * HH + j2] = hnew;
                out[(size_t)(b * TT + t) * (2 * HH) + dir * HH + j2] = hnew;
            }
        }
        dir_barrier(dir);
    }
}

// ---------------------------------------------------------------------------
extern "C" void kernel_launch(void* const* d_in, const int* in_sizes, int n_in,
                              void* d_out, int out_size) {
    (void)in_sizes; (void)n_in; (void)out_size;
    const float* x     = (const float*)d_in[0];
    const float* hf0   = (const float*)d_in[1];
    const float* hb0   = (const float*)d_in[2];
    const float* Whr_f = (const float*)d_in[3];
    const float* Wxr_f = (const float*)d_in[4];
    const float* br_f  = (const float*)d_in[5];
    const float* Whz_f = (const float*)d_in[6];
    const float* Wxz_f = (const float*)d_in[7];
    const float* bz_f  = (const float*)d_in[8];
    const float* Whh_f = (const float*)d_in[9];
    const float* Wxh_f = (const float*)d_in[10];
    const float* bh_f  = (const float*)d_in[11];
    const float* Whr_b = (const float*)d_in[12];
    const float* Wxr_b = (const float*)d_in[13];
    const float* br_b  = (const float*)d_in[14];
    const float* Whz_b = (const float*)d_in[15];
    const float* Wxz_b = (const float*)d_in[16];
    const float* bz_b  = (const float*)d_in[17];
    const float* Whh_b = (const float*)d_in[18];
    const float* Wxh_b = (const float*)d_in[19];
    const float* bh_b  = (const float*)d_in[20];
    float* out = (float*)d_out;

    dim3 g1(TT * BB / 64, HH / 32, 6);
    inproj_kernel<<<g1, 256>>>(x,
        Wxr_f, br_f, Wxz_f, bz_f, Wxh_f, bh_f,
        Wxr_b, br_b, Wxz_b, bz_b, Wxh_b, bh_b);

    gru_rec_kernel<<<2 * NCTA_DIR, 256>>>(hf0, hb0,
        Whr_f, Whz_f, Whh_f, Whr_b, Whz_b, Whh_b, out);
}

// round 3
// speedup vs baseline: 2.0170x; 2.0170x over previous
#include <cuda_runtime.h>

#define BB 64
#define TT 512
#define II 512
#define HH 1024
#define NCTA_DIR 64   // CTAs per direction; 128 total <= 148 SMs -> all co-resident

// ---------------- scratch (device globals; no allocations allowed) ----------
__device__ float g_Xrz[2][TT][BB][2 * HH]; // x@W_xr|x@W_xz (+bias), combined cols
__device__ float g_Xh [2][TT][BB][HH];     // x@W_xh (+bias)
__device__ float g_h  [2][BB][HH];         // current hidden state per direction
__device__ float g_RH [2][BB][HH];         // R * h   (phase1 -> phase2)
__device__ float g_Z  [2][BB][HH];         // Z gate  (phase1 -> phase2)
__device__ unsigned g_bar_count[2];
__device__ unsigned g_bar_gen[2];

// ------------- per-direction software grid barrier (generation-based) -------
__device__ __forceinline__ void dir_barrier(int dir) {
    __syncthreads();
    if (threadIdx.x == 0) {
        volatile unsigned* vgen = (volatile unsigned*)&g_bar_gen[dir];
        unsigned my = *vgen;
        __threadfence();
        unsigned a = atomicAdd(&g_bar_count[dir], 1u);
        if (a == NCTA_DIR - 1) {
            g_bar_count[dir] = 0;
            __threadfence();
            atomicAdd(&g_bar_gen[dir], 1u);
        } else {
            while (*vgen == my) { }
            __threadfence();
        }
    }
    __syncthreads();
}

// ---------------- input projection: 6x GEMM (32768x512)@(512x1024)+bias -----
// CTA: 256 threads -> 128x64 tile, 32 outputs/thread (8 rows x 4 cols)
__global__ void __launch_bounds__(256) inproj_kernel(
    const float* __restrict__ x,
    const float* __restrict__ Wr_f, const float* __restrict__ br_f,
    const float* __restrict__ Wz_f, const float* __restrict__ bz_f,
    const float* __restrict__ Wh_f, const float* __restrict__ bh_f,
    const float* __restrict__ Wr_b, const float* __restrict__ br_b,
    const float* __restrict__ Wz_b, const float* __restrict__ bz_b,
    const float* __restrict__ Wh_b, const float* __restrict__ bh_b)
{
    const int mat  = blockIdx.z;   // 0..5 : dir*3 + gate
    const int dir  = mat / 3;
    const int gate = mat % 3;      // 0=r, 1=z, 2=h
    const float* W; const float* bias;
    switch (mat) {
        case 0: W = Wr_f; bias = br_f; break;
        case 1: W = Wz_f; bias = bz_f; break;
        case 2: W = Wh_f; bias = bh_f; break;
        case 3: W = Wr_b; bias = br_b; break;
        case 4: W = Wz_b; bias = bz_b; break;
        default: W = Wh_b; bias = bh_b; break;
    }

    const int mTile = blockIdx.x;             // 256 row tiles of 128
    const int cTile = blockIdx.y;             // 16 col tiles of 64
    const int w     = threadIdx.x >> 5;       // warp 0..7
    const int lane  = threadIdx.x & 31;
    const int hf    = lane >> 4;              // half-warp
    const int rbase = w * 16 + hf * 8;        // 8 rows per thread
    const int jc    = cTile * 64 + (lane & 15) * 4;  // 4 cols per thread

    __shared__ float xs[128][64];
    float acc[8][4];
    #pragma unroll
    for (int r = 0; r < 8; ++r)
        #pragma unroll
        for (int c = 0; c < 4; ++c) acc[r][c] = 0.f;

    const float* xbase = x + (size_t)(mTile * 128) * II;

    #pragma unroll 1
    for (int kb = 0; kb < II; kb += 64) {
        // stage 128x64 x-tile
        #pragma unroll
        for (int u = 0; u < 8; ++u) {
            int e  = threadIdx.x + 256 * u;     // 0..2047
            int r  = e >> 4;
            int c4 = (e & 15) * 4;
            *(float4*)&xs[r][c4] = *(const float4*)(xbase + r * II + kb + c4);
        }
        __syncthreads();
        #pragma unroll
        for (int k4 = 0; k4 < 16; ++k4) {
            const int k = kb + 4 * k4;
            const float4 w0 = *(const float4*)&W[(k + 0) * HH + jc];
            const float4 w1 = *(const float4*)&W[(k + 1) * HH + jc];
            const float4 w2 = *(const float4*)&W[(k + 2) * HH + jc];
            const float4 w3 = *(const float4*)&W[(k + 3) * HH + jc];
            #pragma unroll
            for (int r = 0; r < 8; ++r) {
                float4 xv = *(const float4*)&xs[rbase + r][4 * k4];
                acc[r][0] = fmaf(xv.x, w0.x, acc[r][0]);
                acc[r][1] = fmaf(xv.x, w0.y, acc[r][1]);
                acc[r][2] = fmaf(xv.x, w0.z, acc[r][2]);
                acc[r][3] = fmaf(xv.x, w0.w, acc[r][3]);
                acc[r][0] = fmaf(xv.y, w1.x, acc[r][0]);
                acc[r][1] = fmaf(xv.y, w1.y, acc[r][1]);
                acc[r][2] = fmaf(xv.y, w1.z, acc[r][2]);
                acc[r][3] = fmaf(xv.y, w1.w, acc[r][3]);
                acc[r][0] = fmaf(xv.z, w2.x, acc[r][0]);
                acc[r][1] = fmaf(xv.z, w2.y, acc[r][1]);
                acc[r][2] = fmaf(xv.z, w2.z, acc[r][2]);
                acc[r][3] = fmaf(xv.z, w2.w, acc[r][3]);
                acc[r][0] = fmaf(xv.w, w3.x, acc[r][0]);
                acc[r][1] = fmaf(xv.w, w3.y, acc[r][1]);
                acc[r][2] = fmaf(xv.w, w3.z, acc[r][2]);
                acc[r][3] = fmaf(xv.w, w3.w, acc[r][3]);
            }
        }
        __syncthreads();
    }

    const float4 bv = *(const float4*)&bias[jc];
    #pragma unroll
    for (int r = 0; r < 8; ++r) {
        int row = mTile * 128 + rbase + r;   // row = b*T + t
        int b   = row >> 9;                  // /512
        int t   = row & (TT - 1);
        float4 v;
        v.x = acc[r][0] + bv.x;
        v.y = acc[r][1] + bv.y;
        v.z = acc[r][2] + bv.z;
        v.w = acc[r][3] + bv.w;
        if (gate == 0)      *(float4*)&g_Xrz[dir][t][b][jc]      = v;
        else if (gate == 1) *(float4*)&g_Xrz[dir][t][b][HH + jc] = v;
        else                *(float4*)&g_Xh [dir][t][b][jc]      = v;
    }
}

// ---------------- persistent bidirectional GRU recurrence -------------------
// 128 CTAs x 256 threads, 1 CTA/SM. All recurrent weights this CTA ever needs
// are cached in SMEM once (192KB), so the per-step inner loops read only SMEM.
// Dynamic smem layout (floats):
//   Wrz4 [1024*32]  : phase1 weights, [(k>>2)*128 + lane*4 + (k&3)]
//   Wh24 [1024*16]  : phase2 weights, [(k>>2)*64  + lane2*4 + (k&3)]
//   ts   [64*64]    : staging tile for h / RH
#define SMEM_WRZ 0
#define SMEM_WH2 (1024 * 32)
#define SMEM_TS  (1024 * 48)
#define SMEM_FLOATS (1024 * 48 + 64 * 64)

__global__ void __launch_bounds__(256) gru_rec_kernel(
    const float* __restrict__ hf0, const float* __restrict__ hb0,
    const float* __restrict__ Whr_f, const float* __restrict__ Whz_f, const float* __restrict__ Whh_f,
    const float* __restrict__ Whr_b, const float* __restrict__ Whz_b, const float* __restrict__ Whh_b,
    float* __restrict__ out)
{
    extern __shared__ float sm[];
    float* Wrz4 = sm + SMEM_WRZ;
    float* Wh24 = sm + SMEM_WH2;
    float (*ts)[64] = (float(*)[64])(sm + SMEM_TS);

    const int dir = blockIdx.x >> 6;
    const int c   = blockIdx.x & 63;

    const float* __restrict__ Whr = dir ? Whr_b : Whr_f;
    const float* __restrict__ Whz = dir ? Whz_b : Whz_f;
    const float* __restrict__ Whh = dir ? Whh_b : Whh_f;
    const float* __restrict__ h0  = dir ? hb0   : hf0;

    float* __restrict__ hstate = &g_h [dir][0][0];
    float* __restrict__ RH     = &g_RH[dir][0][0];
    float* __restrict__ Zb     = &g_Z [dir][0][0];

    // phase1 geometry: 32 combined cols/CTA over 2048; 8 rows/thread
    const int lane1 = threadIdx.x & 31;
    const int rg1   = (threadIdx.x >> 5) * 8;
    const int jj    = c * 32 + lane1;            // 0..2047 combined [R|Z]
    const float* __restrict__ Wg = (jj < HH) ? Whr : Whz;
    const int jw    = jj & (HH - 1);

    // phase2 geometry: 16 cols/CTA over 1024; 4 rows/thread
    const int lane2 = threadIdx.x & 15;
    const int rg2   = (threadIdx.x >> 4) * 4;
    const int j2    = c * 16 + lane2;

    // ---- one-time: cache this CTA's weight columns into SMEM ----
    {
        const int wp = threadIdx.x >> 5;
        for (int k = wp; k < HH; k += 8)                 // phase1: col = jj
            Wrz4[(k >> 2) * 128 + lane1 * 4 + (k & 3)] = Wg[k * HH + jw];
        const int wp2 = threadIdx.x >> 4;
        for (int k = wp2; k < HH; k += 16)               // phase2: col = j2
            Wh24[(k >> 2) * 64 + lane2 * 4 + (k & 3)] = Whh[k * HH + j2];
    }

    // init hidden state from h_prev (re-done every replay: deterministic)
    {
        int base = c * 1024;
        #pragma unroll
        for (int u = 0; u < 4; ++u)
            hstate[base + u * 256 + threadIdx.x] = h0[base + u * 256 + threadIdx.x];
    }
    dir_barrier(dir);

    for (int step = 0; step < TT; ++step) {
        const int t = dir ? (TT - 1 - step) : step;

        // ------------------ phase 1: [R|Z] = sigmoid(h@W + x) -------------
        const float* __restrict__ xrz = &g_Xrz[dir][t][0][0];
        float xpre[8], hold1[8];
        #pragma unroll
        for (int r = 0; r < 8; ++r) {              // prefetch epilogue operands
            xpre[r]  = __ldg(&xrz[(rg1 + r) * (2 * HH) + jj]);
            hold1[r] = hstate[(rg1 + r) * HH + jw];
        }

        float acc[8] = {0.f,0.f,0.f,0.f,0.f,0.f,0.f,0.f};
        #pragma unroll 1
        for (int kb = 0; kb < HH; kb += 64) {
            #pragma unroll
            for (int u = 0; u < 4; ++u) {
                int e  = threadIdx.x + 256 * u;
                int r  = e >> 4;
                int c4 = (e & 15) * 4;
                *(float4*)&ts[r][c4] = *(const float4*)&hstate[r * HH + kb + c4];
            }
            __syncthreads();
            #pragma unroll
            for (int k4 = 0; k4 < 16; ++k4) {
                const int kk = kb + 4 * k4;
                float4 wv = *(const float4*)&Wrz4[(kk >> 2) * 128 + lane1 * 4];
                #pragma unroll
                for (int r = 0; r < 8; ++r) {
                    float4 hv = *(const float4*)&ts[rg1 + r][4 * k4];
                    acc[r] = fmaf(hv.x, wv.x, acc[r]);
                    acc[r] = fmaf(hv.y, wv.y, acc[r]);
                    acc[r] = fmaf(hv.z, wv.z, acc[r]);
                    acc[r] = fmaf(hv.w, wv.w, acc[r]);
                }
            }
            __syncthreads();
        }
        #pragma unroll
        for (int r = 0; r < 8; ++r) {
            const int b = rg1 + r;
            float pre = acc[r] + xpre[r];
            float s   = 1.f / (1.f + __expf(-pre));
            if (jj < HH) RH[b * HH + jw] = s * hold1[r];
            else         Zb[b * HH + jw] = s;
        }
        dir_barrier(dir);

        // ------------------ phase 2: h = Z*tanh(RH@Whh + xh) + (1-Z)*h ----
        const float* __restrict__ xh = &g_Xh[dir][t][0][0];
        float xp2[4], zv[4], hv2[4];
        #pragma unroll
        for (int r = 0; r < 4; ++r) {
            const int b = rg2 + r;
            xp2[r] = __ldg(&xh[b * HH + j2]);
            zv[r]  = Zb[b * HH + j2];
            hv2[r] = hstate[b * HH + j2];
        }

        float a2[4] = {0.f,0.f,0.f,0.f};
        #pragma unroll 1
        for (int kb = 0; kb < HH; kb += 64) {
            #pragma unroll
            for (int u = 0; u < 4; ++u) {
                int e  = threadIdx.x + 256 * u;
                int r  = e >> 4;
                int c4 = (e & 15) * 4;
                *(float4*)&ts[r][c4] = *(const float4*)&RH[r * HH + kb + c4];
            }
            __syncthreads();
            #pragma unroll
            for (int k4 = 0; k4 < 16; ++k4) {
                const int kk = kb + 4 * k4;
                float4 wv = *(const float4*)&Wh24[(kk >> 2) * 64 + lane2 * 4];
                #pragma unroll
                for (int r = 0; r < 4; ++r) {
                    float4 hv = *(const float4*)&ts[rg2 + r][4 * k4];
                    a2[r] = fmaf(hv.x, wv.x, a2[r]);
                    a2[r] = fmaf(hv.y, wv.y, a2[r]);
                    a2[r] = fmaf(hv.z, wv.z, a2[r]);
                    a2[r] = fmaf(hv.w, wv.w, a2[r]);
                }
            }
            __syncthreads();
        }
        #pragma unroll
        for (int r = 0; r < 4; ++r) {
            const int b = rg2 + r;
            float htil = tanhf(a2[r] + xp2[r]);
            float hnew = zv[r] * htil + (1.f - zv[r]) * hv2[r];
            hstate[b * HH + j2] = hnew;
            out[(size_t)(b * TT + t) * (2 * HH) + dir * HH + j2] = hnew;
        }
        dir_barrier(dir);
    }
}

// ---------------------------------------------------------------------------
extern "C" void kernel_launch(void* const* d_in, const int* in_sizes, int n_in,
                              void* d_out, int out_size) {
    (void)in_sizes; (void)n_in; (void)out_size;
    const float* x     = (const float*)d_in[0];
    const float* hf0   = (const float*)d_in[1];
    const float* hb0   = (const float*)d_in[2];
    const float* Whr_f = (const float*)d_in[3];
    const float* Wxr_f = (const float*)d_in[4];
    const float* br_f  = (const float*)d_in[5];
    const float* Whz_f = (const float*)d_in[6];
    const float* Wxz_f = (const float*)d_in[7];
    const float* bz_f  = (const float*)d_in[8];
    const float* Whh_f = (const float*)d_in[9];
    const float* Wxh_f = (const float*)d_in[10];
    const float* bh_f  = (const float*)d_in[11];
    const float* Whr_b = (const float*)d_in[12];
    const float* Wxr_b = (const float*)d_in[13];
    const float* br_b  = (const float*)d_in[14];
    const float* Whz_b = (const float*)d_in[15];
    const float* Wxz_b = (const float*)d_in[16];
    const float* bz_b  = (const float*)d_in[17];
    const float* Whh_b = (const float*)d_in[18];
    const float* Wxh_b = (const float*)d_in[19];
    const float* bh_b  = (const float*)d_in[20];
    float* out = (float*)d_out;

    static int smem_set = 0;
    if (!smem_set) {
        cudaFuncSetAttribute(gru_rec_kernel,
                             cudaFuncAttributeMaxDynamicSharedMemorySize,
                             SMEM_FLOATS * sizeof(float));
        smem_set = 1;
    }

    dim3 g1(TT * BB / 128, HH / 64, 6);
    inproj_kernel<<<g1, 256>>>(x,
        Wxr_f, br_f, Wxz_f, bz_f, Wxh_f, bh_f,
        Wxr_b, br_b, Wxz_b, bz_b, Wxh_b, bh_b);

    gru_rec_kernel<<<2 * NCTA_DIR, 256, SMEM_FLOATS * sizeof(float)>>>(hf0, hb0,
        Whr_f, Whz_f, Whh_f, Whr_b, Whz_b, Whh_b, out);
}